// round 15
// baseline (speedup 1.0000x reference)
#include <cuda_runtime.h>
#include <cuda_fp16.h>
#include <cstdint>

#define NN 20000
#define EE 160000
#define GG 64
#define MAXD 512
#define WTOT 688128

// ---------------- scratch ----------------------------------------------------
__device__ __align__(16) unsigned short g_xh[NN * 128];
__device__ __align__(16) unsigned short g_xl[NN * 128];
__device__ __align__(16) char           g_a1q[NN * MAXD];   // agg int8 limb1
__device__ __align__(16) char           g_a2q[NN * MAXD];   // agg int8 limb2
__device__ __align__(16) unsigned short g_Ah[NN * MAXD];
__device__ __align__(16) unsigned short g_Al[NN * MAXD];
__device__ __align__(16) unsigned short g_Bh[NN * MAXD];
__device__ __align__(16) unsigned short g_Bl[NN * MAXD];
__device__ __align__(16) char           g_wq1[WTOT];        // Wl int8 limb1
__device__ __align__(16) char           g_wq2[WTOT];        // Wl int8 limb2
__device__ __align__(16) unsigned short g_wrh[WTOT];        // Wr fp16 hi
__device__ __align__(16) unsigned short g_wrl[WTOT];        // Wr fp16 lo
__device__ float g_wls[2304];                               // Wl per-col scales
__device__ float g_scale[8];                                // act tensor maxes
__device__ int   g_deg[NN];
__device__ int   g_rowptr[NN + 1];
__device__ int   g_fill[NN];
__device__ int   g_csr[EE];
__device__ float g_pool[GG * 256];

__constant__ int c_din[6]   = {128, 256, 256, 512, 512, 256};
__constant__ int c_dout[6]  = {256, 256, 512, 512, 256, 256};
__constant__ int c_woff[6]  = {0, 32768, 98304, 229376, 491520, 622592};
__constant__ int c_wsoff[6] = {0, 256, 512, 1024, 1536, 2048};

struct WPtrs { const float* w[12]; };

// ---------------- helpers ----------------------------------------------------
__device__ __forceinline__ uint32_t smem_u32(const void* p) {
    uint32_t a;
    asm("{ .reg .u64 t; cvta.to.shared.u64 t, %1; cvt.u32.u64 %0, t; }" : "=r"(a) : "l"(p));
    return a;
}
__device__ __forceinline__ uint32_t pk2h(float a, float b) {
    uint32_t r;
    asm("cvt.rn.f16x2.f32 %0, %1, %2;" : "=r"(r) : "f"(b), "f"(a));
    return r;
}
__device__ __forceinline__ void split2(float v0, float v1, uint32_t& hp, uint32_t& lp) {
    hp = pk2h(v0, v1);
    __half2 hh = *reinterpret_cast<__half2*>(&hp);
    float2 hf = __half22float2(hh);
    lp = pk2h(v0 - hf.x, v1 - hf.y);
}
__device__ __forceinline__ void quant2(float q, int& q1, int& q2) {
    q = fminf(fmaxf(q, -127.f), 127.f);
    q1 = __float2int_rn(q);
    float r = (q - (float)q1) * 256.f;
    r = fminf(fmaxf(r, -127.f), 127.f);
    q2 = __float2int_rn(r);
}
__device__ __forceinline__ void ldm4(uint32_t* r, uint32_t a) {
    asm volatile("ldmatrix.sync.aligned.m8n8.x4.shared.b16 {%0,%1,%2,%3}, [%4];"
                 : "=r"(r[0]), "=r"(r[1]), "=r"(r[2]), "=r"(r[3]) : "r"(a));
}
__device__ __forceinline__ void ldm2(uint32_t* r, uint32_t a) {
    asm volatile("ldmatrix.sync.aligned.m8n8.x2.shared.b16 {%0,%1}, [%2];"
                 : "=r"(r[0]), "=r"(r[1]) : "r"(a));
}
#define MMA_F16F32(c, a, b)                                                        \
    asm volatile("mma.sync.aligned.m16n8k16.row.col.f32.f16.f16.f32 "              \
        "{%0,%1,%2,%3}, {%4,%5,%6,%7}, {%8,%9}, {%0,%1,%2,%3};"                     \
        : "+f"((c)[0]), "+f"((c)[1]), "+f"((c)[2]), "+f"((c)[3])                    \
        : "r"((a)[0]), "r"((a)[1]), "r"((a)[2]), "r"((a)[3]),                       \
          "r"((b)[0]), "r"((b)[1]))
#define MMA_S8(c, a, b)                                                            \
    asm volatile("mma.sync.aligned.m16n8k32.row.col.s32.s8.s8.s32 "                 \
        "{%0,%1,%2,%3}, {%4,%5,%6,%7}, {%8,%9}, {%0,%1,%2,%3};"                     \
        : "+r"((c)[0]), "+r"((c)[1]), "+r"((c)[2]), "+r"((c)[3])                    \
        : "r"((a)[0]), "r"((a)[1]), "r"((a)[2]), "r"((a)[3]),                       \
          "r"((b)[0]), "r"((b)[1]))
#define CP16(dst, src, sz)                                                         \
    asm volatile("cp.async.cg.shared.global [%0], [%1], 16, %2;"                    \
        :: "r"(dst), "l"(src), "r"(sz) : "memory")
#define CP_COMMIT() asm volatile("cp.async.commit_group;" ::: "memory")
#define CP_WAIT1()  asm volatile("cp.async.wait_group 1;" ::: "memory")
#define CP_WAIT0()  asm volatile("cp.async.wait_group 0;" ::: "memory")

// ---------------- setup kernels ----------------------------------------------
__global__ void k_reset() {
    if (threadIdx.x < 8) g_scale[threadIdx.x] = 0.f;
}
__global__ void k_wscale(WPtrs wp) {
    int li = blockIdx.y;
    int n = blockIdx.x * 256 + threadIdx.x;
    int K = c_din[li], Ncol = c_dout[li];
    if (n >= Ncol) return;
    const float* W = wp.w[2 * li];
    float m = 0.f;
    for (int k = 0; k < K; k++) m = fmaxf(m, fabsf(W[(size_t)k * Ncol + n]));
    g_wls[c_wsoff[li] + n] = fmaxf(m, 1e-20f);
}
__global__ void k_cvtall(const float* __restrict__ x, WPtrs wp) {
    int t = threadIdx.x;
    if (blockIdx.y == 0) {
        int gi = blockIdx.x * 256 + t;
        float mx = 0.f;
        if (gi < NN * 16) {
            const float4* xs = (const float4*)(x + (size_t)gi * 8);
            float4 v0 = xs[0], v1 = xs[1];
            uint32_t h0, l0, h1, l1, h2, l2, h3, l3;
            split2(v0.x, v0.y, h0, l0); split2(v0.z, v0.w, h1, l1);
            split2(v1.x, v1.y, h2, l2); split2(v1.z, v1.w, h3, l3);
            ((uint4*)g_xh)[gi] = make_uint4(h0, h1, h2, h3);
            ((uint4*)g_xl)[gi] = make_uint4(l0, l1, l2, l3);
            mx = fmaxf(fmaxf(fmaxf(fabsf(v0.x), fabsf(v0.y)), fmaxf(fabsf(v0.z), fabsf(v0.w))),
                       fmaxf(fmaxf(fabsf(v1.x), fabsf(v1.y)), fmaxf(fabsf(v1.z), fabsf(v1.w))));
        }
        for (int o = 16; o; o >>= 1) mx = fmaxf(mx, __shfl_xor_sync(0xFFFFFFFFu, mx, o));
        if ((t & 31) == 0) atomicMax((int*)&g_scale[0], __float_as_int(mx));
    } else {
        int id = blockIdx.y - 1, li = id >> 1, lr = id & 1;
        int K = c_din[li], Ncol = c_dout[li];
        int i = blockIdx.x * 256 + t;
        if (i < K * Ncol) {
            int k = i / Ncol, n = i % Ncol;
            float v = wp.w[id][i];
            if (lr == 0) {  // Wl -> int8 2-limb, per-column scale
                float s = g_wls[c_wsoff[li] + n];
                int q1, q2;
                quant2(v * (127.f / s), q1, q2);
                g_wq1[(size_t)c_woff[li] + (size_t)n * K + k] = (char)q1;
                g_wq2[(size_t)c_woff[li] + (size_t)n * K + k] = (char)q2;
            } else {        // Wr -> fp16 hi/lo planes
                uint32_t hp, lp;
                split2(v, 0.f, hp, lp);
                g_wrh[(size_t)c_woff[li] + (size_t)n * K + k] = (unsigned short)(hp & 0xFFFFu);
                g_wrl[(size_t)c_woff[li] + (size_t)n * K + k] = (unsigned short)(lp & 0xFFFFu);
            }
        }
    }
}

// ---------------- CSR build ---------------------------------------------------
__global__ void k_count(const int* __restrict__ ei) {
    int e = blockIdx.x * blockDim.x + threadIdx.x;
    if (e < EE) atomicAdd(&g_deg[ei[EE + e]], 1);
}
__global__ void k_scan() {
    __shared__ int part[1024];
    int t = threadIdx.x;
    const int CH = (NN + 1023) / 1024;
    int base = t * CH, s = 0;
    for (int i = 0; i < CH; i++) { int idx = base + i; if (idx < NN) s += g_deg[idx]; }
    part[t] = s;
    __syncthreads();
    for (int off = 1; off < 1024; off <<= 1) {
        int v = (t >= off) ? part[t - off] : 0;
        __syncthreads(); part[t] += v; __syncthreads();
    }
    int run = (t == 0) ? 0 : part[t - 1];
    for (int i = 0; i < CH; i++) {
        int idx = base + i;
        if (idx < NN) {
            int c = g_deg[idx];
            g_rowptr[idx] = run; g_fill[idx] = run; run += c;
            g_deg[idx] = 0;
        }
    }
    if (t == 1023) g_rowptr[NN] = part[1023];
}
__global__ void k_fillcsr(const int* __restrict__ ei) {
    int e = blockIdx.x * blockDim.x + threadIdx.x;
    if (e < EE) { int d = ei[EE + e]; int p = atomicAdd(&g_fill[d], 1); g_csr[p] = ei[e]; }
}

// ---------------- mean aggregation -> int8 limbs (scale known a priori) -------
__device__ __forceinline__ void acc_u2(float* a, uint2 h, uint2 l) {
    float2 f0 = __half22float2(*reinterpret_cast<__half2*>(&h.x));
    float2 f1 = __half22float2(*reinterpret_cast<__half2*>(&h.y));
    float2 g0 = __half22float2(*reinterpret_cast<__half2*>(&l.x));
    float2 g1 = __half22float2(*reinterpret_cast<__half2*>(&l.y));
    a[0] += f0.x + g0.x;
    a[1] += f0.y + g0.y;
    a[2] += f1.x + g1.x;
    a[3] += f1.y + g1.y;
}

__global__ void k_agg(const unsigned short* __restrict__ ph, const unsigned short* __restrict__ pl,
                      int K, const float* __restrict__ scl) {
    int node = blockIdx.x * 8 + (threadIdx.x >> 5);
    if (node >= NN) return;
    int lane = threadIdx.x & 31;
    int rs = K >> 2;
    int cidx = blockIdx.y * 32 + lane;
    int beg = g_rowptr[node], end = g_rowptr[node + 1];
    const uint2* bh = (const uint2*)ph;
    const uint2* bl = (const uint2*)pl;

    float a0[4], a1[4], a2[4], a3[4];
#pragma unroll
    for (int j = 0; j < 4; j++) { a0[j] = 0.f; a1[j] = 0.f; a2[j] = 0.f; a3[j] = 0.f; }

    int e = beg;
    for (; e + 4 <= end; e += 4) {
        int s0 = g_csr[e], s1 = g_csr[e + 1], s2 = g_csr[e + 2], s3 = g_csr[e + 3];
        uint2 h0 = bh[(size_t)s0 * rs + cidx], l0 = bl[(size_t)s0 * rs + cidx];
        uint2 h1 = bh[(size_t)s1 * rs + cidx], l1 = bl[(size_t)s1 * rs + cidx];
        uint2 h2 = bh[(size_t)s2 * rs + cidx], l2 = bl[(size_t)s2 * rs + cidx];
        uint2 h3 = bh[(size_t)s3 * rs + cidx], l3 = bl[(size_t)s3 * rs + cidx];
        acc_u2(a0, h0, l0); acc_u2(a1, h1, l1); acc_u2(a2, h2, l2); acc_u2(a3, h3, l3);
    }
    for (; e < end; e++) {
        int s = g_csr[e];
        acc_u2(a0, bh[(size_t)s * rs + cidx], bl[(size_t)s * rs + cidx]);
    }

    int d = end - beg;
    float inv = 1.0f / (float)(d > 0 ? d : 1);
    float s = fmaxf(*scl, 1e-20f);
    float qs = 127.0f / s;
    uint32_t b1 = 0, b2 = 0;
#pragma unroll
    for (int j = 0; j < 4; j++) {
        float m = ((a0[j] + a1[j]) + (a2[j] + a3[j])) * inv;
        int q1, q2;
        quant2(m * qs, q1, q2);
        b1 |= ((uint32_t)q1 & 0xFFu) << (8 * j);
        b2 |= ((uint32_t)q2 & 0xFFu) << (8 * j);
    }
    size_t wi = ((size_t)node * K >> 2) + cidx;
    ((uint32_t*)g_a1q)[wi] = b1;
    ((uint32_t*)g_a2q)[wi] = b2;
}

// ---------------- mixed GEMM: phase1 int8 (agg@Wl), phase2 fp16 (h@Wr) --------
// phase1 stage layout (48B rows): A1 0, A2 6144, B1 12288, B2 18432
// phase2 stage layout (R12, 64B rows): AH 0, AL 8192, BH 16384, BL 24576
#define P1_A1 0
#define P1_A2 6144
#define P1_B1 12288
#define P1_B2 18432
#define P2_AH 0
#define P2_AL 8192
#define P2_BH 16384
#define P2_BL 24576
#define STAGE_B 32768
#define SMEM_BYTES 65536

template <bool LEAKY>
__global__ void __launch_bounds__(256) k_gemm_tc(
    const char* __restrict__ a1q, const char* __restrict__ a2q,
    const unsigned short* __restrict__ hh, const unsigned short* __restrict__ hl,
    const char* __restrict__ wq1, const char* __restrict__ wq2,
    const float* __restrict__ wls,
    const unsigned short* __restrict__ wrh, const unsigned short* __restrict__ wrl,
    const float* __restrict__ bias,
    unsigned short* __restrict__ Oh, unsigned short* __restrict__ Ol,
    int K, int DOUT, const float* __restrict__ scIn, int* __restrict__ scOut)
{
    extern __shared__ char smem[];
    const uint32_t sb = smem_u32(smem);
    const int t = threadIdx.x, lane = t & 31, wid = t >> 5;
    const int wr = wid >> 2, wc = wid & 3;
    const int m0 = blockIdx.y * 128, n0 = blockIdx.x * 128;
    const int nc = K / 32;

    // ---- shared fill constants
    // phase1: thread -> (row = t>>1, granule g = t&1) per tile (32B rows -> 48B padded)
    const int f1row = t >> 1;
    const int f1g = t & 1;
    const uint32_t dq = (uint32_t)f1row * 48 + (uint32_t)f1g * 16;
    const int gra1 = m0 + f1row;
    const uint32_t szq = (gra1 < NN) ? 16u : 0u;
    const size_t aqoff = (size_t)(gra1 < NN ? gra1 : NN - 1) * K + f1g * 16;
    const size_t bqoff = (size_t)(n0 + f1row) * K + f1g * 16;
    // phase2 (R12): thread -> (row = t>>2, granule g = t&3), 64B rows swizzled
    const int f2row = t >> 2;
    const int f2g = t & 3;
    const uint32_t d0 = (uint32_t)f2row * 64 + (((uint32_t)f2g * 16) ^ (((uint32_t)f2row & 6) << 3));
    const uint32_t d1 = d0 + 4096;
    const int gr0 = m0 + f2row, gr1 = m0 + f2row + 64;
    const uint32_t sz0 = (gr0 < NN) ? 16u : 0u;
    const uint32_t sz1 = (gr1 < NN) ? 16u : 0u;
    const size_t aoff0 = (size_t)(gr0 < NN ? gr0 : NN - 1) * K + f2g * 8;
    const size_t aoff1 = (size_t)(gr1 < NN ? gr1 : NN - 1) * K + f2g * 8;
    const size_t boff0 = (size_t)(n0 + f2row) * K + f2g * 8;
    const size_t boff1 = (size_t)(n0 + f2row + 64) * K + f2g * 8;

    // ---- MMA fragment address constants (shared pattern)
    const uint32_t fxor = ((uint32_t)(lane & 6)) << 3;
    const int ra = wr * 64 + (lane & 7) + ((lane >> 3) & 1) * 8;
    const uint32_t agsel = ((uint32_t)(lane >> 4)) * 16;
    const int rb = wc * 32 + (lane & 7);
    const uint32_t bgsel = ((uint32_t)((lane >> 3) & 1)) * 16;

#define FILL1(ch, stg) do {                                                        \
    int kb_ = (ch) * 32;                                                           \
    uint32_t s0_ = sb + (uint32_t)(stg) * STAGE_B;                                 \
    CP16(s0_ + P1_A1 + dq, a1q + aqoff + kb_, szq);                                \
    CP16(s0_ + P1_A2 + dq, a2q + aqoff + kb_, szq);                                \
    CP16(s0_ + P1_B1 + dq, wq1 + bqoff + kb_, 16u);                                \
    CP16(s0_ + P1_B2 + dq, wq2 + bqoff + kb_, 16u);                                \
    CP_COMMIT();                                                                   \
} while (0)

#define FILL2(ch, stg) do {                                                        \
    int kb_ = (ch) * 32;                                                           \
    uint32_t s0_ = sb + (uint32_t)(stg) * STAGE_B;                                 \
    CP16(s0_ + P2_AH + d0, hh + aoff0 + kb_, sz0);                                 \
    CP16(s0_ + P2_AH + d1, hh + aoff1 + kb_, sz1);                                 \
    CP16(s0_ + P2_AL + d0, hl + aoff0 + kb_, sz0);                                 \
    CP16(s0_ + P2_AL + d1, hl + aoff1 + kb_, sz1);                                 \
    CP16(s0_ + P2_BH + d0, wrh + boff0 + kb_, 16u);                                \
    CP16(s0_ + P2_BH + d1, wrh + boff1 + kb_, 16u);                                \
    CP16(s0_ + P2_BL + d0, wrl + boff0 + kb_, 16u);                                \
    CP16(s0_ + P2_BL + d1, wrl + boff1 + kb_, 16u);                                \
    CP_COMMIT();                                                                   \
} while (0)

    // ================= phase 1: int8 agg@Wl =================
    int cm[4][4][4], cc[4][4][4];
#pragma unroll
    for (int i = 0; i < 4; i++)
#pragma unroll
        for (int j = 0; j < 4; j++)
#pragma unroll
            for (int k = 0; k < 4; k++) { cm[i][j][k] = 0; cc[i][j][k] = 0; }

    FILL1(0, 0);
    for (int ch = 0; ch < nc; ch++) {
        __syncthreads();
        if (ch + 1 < nc) { FILL1(ch + 1, (ch + 1) & 1); CP_WAIT1(); }
        else             { FILL2(0, nc & 1); CP_WAIT1(); }
        __syncthreads();

        const uint32_t s0 = sb + (uint32_t)(ch & 1) * STAGE_B;
        uint32_t b1f[4][2], b2f[4][2];
#pragma unroll
        for (int nt = 0; nt < 4; nt++) {
            uint32_t base = s0 + (uint32_t)(rb + nt * 8) * 48 + bgsel;
            ldm2(b1f[nt], base + P1_B1);
            ldm2(b2f[nt], base + P1_B2);
        }
#pragma unroll
        for (int mt = 0; mt < 4; mt++) {
            uint32_t base = s0 + (uint32_t)(ra + mt * 16) * 48 + agsel;
            uint32_t a1f[4], a2f[4];
            ldm4(a1f, base + P1_A1);
            ldm4(a2f, base + P1_A2);
#pragma unroll
            for (int nt = 0; nt < 4; nt++) {
                MMA_S8(cm[mt][nt], a1f, b1f[nt]);
                MMA_S8(cc[mt][nt], a1f, b2f[nt]);
                MMA_S8(cc[mt][nt], a2f, b1f[nt]);
            }
        }
    }

    // convert s32 accs -> f32 with scales
    float acc[4][4][4];
    {
        float sA = fmaxf(*scIn, 1e-20f);
#pragma unroll
        for (int mt = 0; mt < 4; mt++)
#pragma unroll
            for (int nt = 0; nt < 4; nt++) {
                int c0 = n0 + wc * 32 + nt * 8 + (lane & 3) * 2;
                float2 sw = *(const float2*)(wls + c0);
                float f0 = sA * sw.x * 6.200136e-5f;  // 1/(127*127)
                float f1 = sA * sw.y * 6.200136e-5f;
                acc[mt][nt][0] = ((float)cm[mt][nt][0] + (float)cc[mt][nt][0] * 0.00390625f) * f0;
                acc[mt][nt][1] = ((float)cm[mt][nt][1] + (float)cc[mt][nt][1] * 0.00390625f) * f1;
                acc[mt][nt][2] = ((float)cm[mt][nt][2] + (float)cc[mt][nt][2] * 0.00390625f) * f0;
                acc[mt][nt][3] = ((float)cm[mt][nt][3] + (float)cc[mt][nt][3] * 0.00390625f) * f1;
            }
    }

    // ================= phase 2: fp16 3-term h@Wr (R9/R12-proven) =================
    for (int ch = 0; ch < nc; ch++) {
        __syncthreads();
        int gch = nc + ch;
        if (ch + 1 < nc) { FILL2(ch + 1, (gch + 1) & 1); CP_WAIT1(); }
        else             { CP_WAIT0(); }
        __syncthreads();

        const uint32_t s0 = sb + (uint32_t)(gch & 1) * STAGE_B;
#pragma unroll
        for (int ks = 0; ks < 2; ks++) {
            uint32_t ahf[4][4], alf[4][4], bhf[4][2], blf[4][2];
#pragma unroll
            for (int mt = 0; mt < 4; mt++) {
                uint32_t base = s0 + (uint32_t)(ra + mt * 16) * 64;
                ldm4(ahf[mt], base + P2_AH + (((uint32_t)(ks * 32) + agsel) ^ fxor));
                ldm4(alf[mt], base + P2_AL + (((uint32_t)(ks * 32) + agsel) ^ fxor));
            }
#pragma unroll
            for (int nt = 0; nt < 4; nt++) {
                uint32_t base = s0 + (uint32_t)(rb + nt * 8) * 64;
                ldm2(bhf[nt], base + P2_BH + (((uint32_t)(ks * 32) + bgsel) ^ fxor));
                ldm2(blf[nt], base + P2_BL + (((uint32_t)(ks * 32) + bgsel) ^ fxor));
            }
#pragma unroll
            for (int mt = 0; mt < 4; mt++)
#pragma unroll
                for (int nt = 0; nt < 4; nt++) {
                    MMA_F16F32(acc[mt][nt], ahf[mt], bhf[nt]);
                    MMA_F16F32(acc[mt][nt], ahf[mt], blf[nt]);
                    MMA_F16F32(acc[mt][nt], alf[mt], bhf[nt]);
                }
        }
    }

    // epilogue: bias, optional leaky, hi/lo out, next-layer scale atomicMax
    float mx = 0.f;
#pragma unroll
    for (int mt = 0; mt < 4; mt++) {
        int r0 = m0 + wr * 64 + mt * 16 + (lane >> 2);
        int r1 = r0 + 8;
#pragma unroll
        for (int nt = 0; nt < 4; nt++) {
            int c0 = n0 + wc * 32 + nt * 8 + (lane & 3) * 2;
            float2 b2 = *(const float2*)(bias + c0);
            float v0 = acc[mt][nt][0] + b2.x;
            float v1 = acc[mt][nt][1] + b2.y;
            float v2 = acc[mt][nt][2] + b2.x;
            float v3 = acc[mt][nt][3] + b2.y;
            if (LEAKY) {
                v0 = v0 >= 0.f ? v0 : 0.01f * v0;
                v1 = v1 >= 0.f ? v1 : 0.01f * v1;
                v2 = v2 >= 0.f ? v2 : 0.01f * v2;
                v3 = v3 >= 0.f ? v3 : 0.01f * v3;
            }
            uint32_t hp, lp;
            if (r0 < NN) {
                mx = fmaxf(mx, fmaxf(fabsf(v0), fabsf(v1)));
                split2(v0, v1, hp, lp);
                *(uint32_t*)(Oh + (size_t)r0 * DOUT + c0) = hp;
                *(uint32_t*)(Ol + (size_t)r0 * DOUT + c0) = lp;
            }
            if (r1 < NN) {
                mx = fmaxf(mx, fmaxf(fabsf(v2), fabsf(v3)));
                split2(v2, v3, hp, lp);
                *(uint32_t*)(Oh + (size_t)r1 * DOUT + c0) = hp;
                *(uint32_t*)(Ol + (size_t)r1 * DOUT + c0) = lp;
            }
        }
    }
    for (int o = 16; o; o >>= 1) mx = fmaxf(mx, __shfl_xor_sync(0xFFFFFFFFu, mx, o));
    if (lane == 0) atomicMax(scOut, __float_as_int(mx));
}

// ---------------- pool + head --------------------------------------------------
__global__ void k_pool(const unsigned short* __restrict__ Hh,
                       const unsigned short* __restrict__ Hl,
                       const int* __restrict__ batch) {
    __shared__ int ss, ee;
    int gidx = blockIdx.x, f = threadIdx.x;
    if (f == 0) {
        int lo = 0, hi = NN;
        while (lo < hi) { int m = (lo + hi) >> 1; if (batch[m] < gidx) lo = m + 1; else hi = m; }
        ss = lo;
        hi = NN;
        while (lo < hi) { int m = (lo + hi) >> 1; if (batch[m] < gidx + 1) lo = m + 1; else hi = m; }
        ee = lo;
    }
    __syncthreads();
    int s = ss, e = ee;
    float sum = 0.f;
    for (int n = s; n < e; n++) {
        size_t idx = (size_t)n * 256 + f;
        sum += __half2float(((const __half*)Hh)[idx]) + __half2float(((const __half*)Hl)[idx]);
    }
    int c = e - s; if (c < 1) c = 1;
    g_pool[gidx * 256 + f] = sum / (float)c;
}
__global__ void k_final(const float* __restrict__ Wlin, const float* __restrict__ blin,
                        float* __restrict__ out) {
    int idx = threadIdx.x;
    if (idx >= GG * 6) return;
    int g = idx / 6, o = idx % 6;
    float s = blin[o];
#pragma unroll 8
    for (int k = 0; k < 256; k++) s += g_pool[g * 256 + k] * Wlin[k * 6 + o];
    out[idx] = s;
}

// ---------------- launcher ------------------------------------------------------
extern "C" void kernel_launch(void* const* d_in, const int* in_sizes, int n_in,
                              void* d_out, int out_size) {
    const float* x     = (const float*)d_in[0];
    const int*   ei    = (const int*)d_in[1];
    const int*   batch = (const int*)d_in[2];
    WPtrs wp;
    const float* blp[6];
    for (int l = 0; l < 6; l++) {
        wp.w[2 * l]     = (const float*)d_in[3 + 3 * l];  // Wl
        blp[l]          = (const float*)d_in[4 + 3 * l];
        wp.w[2 * l + 1] = (const float*)d_in[5 + 3 * l];  // Wr
    }
    const float* Wlin = (const float*)d_in[21];
    const float* blin = (const float*)d_in[22];
    float* out = (float*)d_out;

    unsigned short *xh, *xl, *Ah, *Al, *Bh, *Bl, *wrh, *wrl;
    char *a1q, *a2q, *wq1, *wq2;
    float *wls, *scl;
    cudaGetSymbolAddress((void**)&xh, g_xh);   cudaGetSymbolAddress((void**)&xl, g_xl);
    cudaGetSymbolAddress((void**)&a1q, g_a1q); cudaGetSymbolAddress((void**)&a2q, g_a2q);
    cudaGetSymbolAddress((void**)&Ah, g_Ah);   cudaGetSymbolAddress((void**)&Al, g_Al);
    cudaGetSymbolAddress((void**)&Bh, g_Bh);   cudaGetSymbolAddress((void**)&Bl, g_Bl);
    cudaGetSymbolAddress((void**)&wq1, g_wq1); cudaGetSymbolAddress((void**)&wq2, g_wq2);
    cudaGetSymbolAddress((void**)&wrh, g_wrh); cudaGetSymbolAddress((void**)&wrl, g_wrl);
    cudaGetSymbolAddress((void**)&wls, g_wls); cudaGetSymbolAddress((void**)&scl, g_scale);

    cudaFuncSetAttribute(k_gemm_tc<true>,  cudaFuncAttributeMaxDynamicSharedMemorySize, SMEM_BYTES);
    cudaFuncSetAttribute(k_gemm_tc<false>, cudaFuncAttributeMaxDynamicSharedMemorySize, SMEM_BYTES);

    const int din[6]  = {128, 256, 256, 512, 512, 256};
    const int dout[6] = {256, 256, 512, 512, 256, 256};
    const int woff[6] = {0, 32768, 98304, 229376, 491520, 622592};
    const int wsoff[6] = {0, 256, 512, 1024, 1536, 2048};

    // setup
    k_reset<<<1, 32>>>();
    k_wscale<<<dim3(2, 6), 256>>>(wp);
    k_cvtall<<<dim3(1250, 13), 256>>>(x, wp);
    k_count<<<(EE + 255) / 256, 256>>>(ei);
    k_scan<<<1, 1024>>>();
    k_fillcsr<<<(EE + 255) / 256, 256>>>(ei);

    const unsigned short* inh = xh; const unsigned short* inl = xl;
    for (int l = 0; l < 6; l++) {
        unsigned short* oh = (l & 1) ? Bh : Ah;
        unsigned short* ol = (l & 1) ? Bl : Al;
        dim3 agrid((NN + 7) / 8, din[l] >> 7);
        k_agg<<<agrid, 256>>>(inh, inl, din[l], scl + l);
        dim3 grid(dout[l] / 128, (NN + 127) / 128);
        if (l < 5)
            k_gemm_tc<true><<<grid, 256, SMEM_BYTES>>>(
                a1q, a2q, inh, inl, wq1 + woff[l], wq2 + woff[l], wls + wsoff[l],
                wrh + woff[l], wrl + woff[l], blp[l], oh, ol, din[l], dout[l],
                scl + l, (int*)(scl + l + 1));
        else
            k_gemm_tc<false><<<grid, 256, SMEM_BYTES>>>(
                a1q, a2q, inh, inl, wq1 + woff[l], wq2 + woff[l], wls + wsoff[l],
                wrh + woff[l], wrl + woff[l], blp[l], oh, ol, din[l], dout[l],
                scl + l, (int*)(scl + l + 1));
        inh = oh; inl = ol;
    }
    k_pool<<<GG, 256>>>(inh, inl, batch);
    k_final<<<1, 384>>>(Wlin, blin, out);
}

// round 16
// speedup vs baseline: 1.8626x; 1.8626x over previous
#include <cuda_runtime.h>
#include <cuda_fp16.h>
#include <cstdint>

#define NN 20000
#define EE 160000
#define GG 64
#define MAXD 512
#define WTOT 688128

// ---------------- scratch ----------------------------------------------------
__device__ __align__(16) unsigned short g_xh[NN * 128];
__device__ __align__(16) unsigned short g_xl[NN * 128];
__device__ __align__(16) unsigned short g_agh[NN * MAXD];
__device__ __align__(16) unsigned short g_agl[NN * MAXD];
__device__ __align__(16) unsigned short g_Ah[NN * MAXD];
__device__ __align__(16) unsigned short g_Al[NN * MAXD];
__device__ __align__(16) unsigned short g_Bh[NN * MAXD];
__device__ __align__(16) unsigned short g_Bl[NN * MAXD];
__device__ __align__(16) float          g_f32[NN * MAXD];   // f32 copy for agg/pool
__device__ __align__(16) unsigned short g_wlh[WTOT];
__device__ __align__(16) unsigned short g_wll[WTOT];
__device__ __align__(16) unsigned short g_wrh[WTOT];
__device__ __align__(16) unsigned short g_wrl[WTOT];
__device__ int   g_deg[NN];          // zero at load; k_scan re-zeroes
__device__ int   g_rowptr[NN + 1];
__device__ int   g_fill[NN];
__device__ int   g_csr[EE];
__device__ float g_pool[GG * 256];

__constant__ int c_din[6]  = {128, 256, 256, 512, 512, 256};
__constant__ int c_dout[6] = {256, 256, 512, 512, 256, 256};
__constant__ int c_woff[6] = {0, 32768, 98304, 229376, 491520, 622592};

struct WPtrs { const float* w[12]; };

// ---------------- helpers ----------------------------------------------------
__device__ __forceinline__ uint32_t smem_u32(const void* p) {
    uint32_t a;
    asm("{ .reg .u64 t; cvta.to.shared.u64 t, %1; cvt.u32.u64 %0, t; }" : "=r"(a) : "l"(p));
    return a;
}
__device__ __forceinline__ uint32_t pk2h(float a, float b) {  // low16=a, high16=b
    uint32_t r;
    asm("cvt.rn.f16x2.f32 %0, %1, %2;" : "=r"(r) : "f"(b), "f"(a));
    return r;
}
__device__ __forceinline__ void split2(float v0, float v1, uint32_t& hp, uint32_t& lp) {
    hp = pk2h(v0, v1);
    __half2 hh = *reinterpret_cast<__half2*>(&hp);
    float2 hf = __half22float2(hh);
    lp = pk2h(v0 - hf.x, v1 - hf.y);
}
__device__ __forceinline__ void ldm4(uint32_t* r, uint32_t a) {
    asm volatile("ldmatrix.sync.aligned.m8n8.x4.shared.b16 {%0,%1,%2,%3}, [%4];"
                 : "=r"(r[0]), "=r"(r[1]), "=r"(r[2]), "=r"(r[3]) : "r"(a));
}
__device__ __forceinline__ void ldm2(uint32_t* r, uint32_t a) {
    asm volatile("ldmatrix.sync.aligned.m8n8.x2.shared.b16 {%0,%1}, [%2];"
                 : "=r"(r[0]), "=r"(r[1]) : "r"(a));
}
#define MMA_F16F32(c, a, b)                                                        \
    asm volatile("mma.sync.aligned.m16n8k16.row.col.f32.f16.f16.f32 "              \
        "{%0,%1,%2,%3}, {%4,%5,%6,%7}, {%8,%9}, {%0,%1,%2,%3};"                     \
        : "+f"((c)[0]), "+f"((c)[1]), "+f"((c)[2]), "+f"((c)[3])                    \
        : "r"((a)[0]), "r"((a)[1]), "r"((a)[2]), "r"((a)[3]),                       \
          "r"((b)[0]), "r"((b)[1]))
#define CP16(dst, src, sz)                                                         \
    asm volatile("cp.async.cg.shared.global [%0], [%1], 16, %2;"                    \
        :: "r"(dst), "l"(src), "r"(sz) : "memory")
#define CP_COMMIT() asm volatile("cp.async.commit_group;" ::: "memory")
#define CP_WAIT1()  asm volatile("cp.async.wait_group 1;" ::: "memory")
#define CP_WAIT0()  asm volatile("cp.async.wait_group 0;" ::: "memory")

// ---------------- fused convert: x split + weight transpose/split -----------
__global__ void k_cvtall(const float* __restrict__ x, WPtrs wp) {
    int t = threadIdx.x;
    if (blockIdx.y == 0) {
        int gi = blockIdx.x * 256 + t;
        if (gi < NN * 16) {
            const float4* xs = (const float4*)(x + (size_t)gi * 8);
            float4 v0 = xs[0], v1 = xs[1];
            uint32_t h0, l0, h1, l1, h2, l2, h3, l3;
            split2(v0.x, v0.y, h0, l0); split2(v0.z, v0.w, h1, l1);
            split2(v1.x, v1.y, h2, l2); split2(v1.z, v1.w, h3, l3);
            ((uint4*)g_xh)[gi] = make_uint4(h0, h1, h2, h3);
            ((uint4*)g_xl)[gi] = make_uint4(l0, l1, l2, l3);
        }
    } else {
        int id = blockIdx.y - 1, li = id >> 1, lr = id & 1;
        int K = c_din[li], Ncol = c_dout[li];
        int i = blockIdx.x * 256 + t;
        if (i < K * Ncol) {
            int k = i / Ncol, n = i % Ncol;
            float v = wp.w[id][i];
            uint32_t hp, lp;
            split2(v, 0.f, hp, lp);
            unsigned short* wh = (lr ? g_wrh : g_wlh) + c_woff[li];
            unsigned short* wl = (lr ? g_wrl : g_wll) + c_woff[li];
            wh[(size_t)n * K + k] = (unsigned short)(hp & 0xFFFFu);
            wl[(size_t)n * K + k] = (unsigned short)(lp & 0xFFFFu);
        }
    }
}

// ---------------- CSR build (parallel; scan self-zeroes g_deg) --------------
__global__ void k_count(const int* __restrict__ ei) {
    int e = blockIdx.x * blockDim.x + threadIdx.x;
    if (e < EE) atomicAdd(&g_deg[ei[EE + e]], 1);
}
__global__ void k_scan() {
    __shared__ int part[1024];
    int t = threadIdx.x;
    const int CH = (NN + 1023) / 1024;
    int base = t * CH, s = 0;
    for (int i = 0; i < CH; i++) { int idx = base + i; if (idx < NN) s += g_deg[idx]; }
    part[t] = s;
    __syncthreads();
    for (int off = 1; off < 1024; off <<= 1) {
        int v = (t >= off) ? part[t - off] : 0;
        __syncthreads(); part[t] += v; __syncthreads();
    }
    int run = (t == 0) ? 0 : part[t - 1];
    for (int i = 0; i < CH; i++) {
        int idx = base + i;
        if (idx < NN) {
            int c = g_deg[idx];
            g_rowptr[idx] = run; g_fill[idx] = run; run += c;
            g_deg[idx] = 0;
        }
    }
    if (t == 1023) g_rowptr[NN] = part[1023];
}
__global__ void k_fillcsr(const int* __restrict__ ei) {
    int e = blockIdx.x * blockDim.x + threadIdx.x;
    if (e < EE) { int d = ei[EE + e]; int p = atomicAdd(&g_fill[d], 1); g_csr[p] = ei[e]; }
}

// ---------------- mean aggregation from f32: warp=(node, 128-chunk) ---------
__global__ void k_agg(const float* __restrict__ in,
                      unsigned short* __restrict__ oh, unsigned short* __restrict__ ol, int K) {
    int node = blockIdx.x * 8 + (threadIdx.x >> 5);
    if (node >= NN) return;
    int lane = threadIdx.x & 31;
    int rs = K >> 2;                       // float4 per row
    int cidx = blockIdx.y * 32 + lane;
    int beg = g_rowptr[node], end = g_rowptr[node + 1];
    const float4* base = (const float4*)in;

    float a0[4], a1[4], a2[4], a3[4];
#pragma unroll
    for (int j = 0; j < 4; j++) { a0[j] = 0.f; a1[j] = 0.f; a2[j] = 0.f; a3[j] = 0.f; }

    int e = beg;
    for (; e + 4 <= end; e += 4) {
        int s0 = g_csr[e], s1 = g_csr[e + 1], s2 = g_csr[e + 2], s3 = g_csr[e + 3];
        float4 v0 = base[(size_t)s0 * rs + cidx];
        float4 v1 = base[(size_t)s1 * rs + cidx];
        float4 v2 = base[(size_t)s2 * rs + cidx];
        float4 v3 = base[(size_t)s3 * rs + cidx];
        a0[0] += v0.x; a0[1] += v0.y; a0[2] += v0.z; a0[3] += v0.w;
        a1[0] += v1.x; a1[1] += v1.y; a1[2] += v1.z; a1[3] += v1.w;
        a2[0] += v2.x; a2[1] += v2.y; a2[2] += v2.z; a2[3] += v2.w;
        a3[0] += v3.x; a3[1] += v3.y; a3[2] += v3.z; a3[3] += v3.w;
    }
    for (; e < end; e++) {
        float4 v = base[(size_t)g_csr[e] * rs + cidx];
        a0[0] += v.x; a0[1] += v.y; a0[2] += v.z; a0[3] += v.w;
    }

    int d = end - beg;
    float inv = 1.0f / (float)(d > 0 ? d : 1);
    float m[4];
#pragma unroll
    for (int j = 0; j < 4; j++) m[j] = ((a0[j] + a1[j]) + (a2[j] + a3[j])) * inv;
    uint32_t hp0, lp0, hp1, lp1;
    split2(m[0], m[1], hp0, lp0);
    split2(m[2], m[3], hp1, lp1);
    ((uint2*)oh)[(size_t)node * rs + cidx] = make_uint2(hp0, hp1);
    ((uint2*)ol)[(size_t)node * rs + cidx] = make_uint2(lp0, lp1);
}

// ---------------- fp16 3-term dual GEMM: 64x128 tile, 2 CTAs/SM -------------
#define T_AH 0
#define T_AL 4096
#define T_BH 8192
#define T_BL 16384
#define STAGE_B 24576
#define SMEM_BYTES 49152

template <bool LEAKY>
__global__ void __launch_bounds__(256) k_gemm_tc(
    const unsigned short* __restrict__ a1h, const unsigned short* __restrict__ a1l,
    const unsigned short* __restrict__ a2h, const unsigned short* __restrict__ a2l,
    const unsigned short* __restrict__ b1h, const unsigned short* __restrict__ b1l,
    const unsigned short* __restrict__ b2h, const unsigned short* __restrict__ b2l,
    const float* __restrict__ bias,
    unsigned short* __restrict__ Oh, unsigned short* __restrict__ Ol,
    float* __restrict__ Of,
    int K, int DOUT)
{
    extern __shared__ char smem[];
    const uint32_t sb = smem_u32(smem);
    const int t = threadIdx.x, lane = t & 31, wid = t >> 5;
    const int wr = wid >> 2, wc = wid & 3;   // 2 x 4 warp grid, warp tile 32x32
    const int m0 = blockIdx.y * 64, n0 = blockIdx.x * 128;
    const int nc = K / 32, tot = 2 * nc;

    float acc[2][4][4];
#pragma unroll
    for (int i = 0; i < 2; i++)
#pragma unroll
        for (int j = 0; j < 4; j++)
#pragma unroll
            for (int k = 0; k < 4; k++) acc[i][j][k] = 0.f;

    // fill constants: row0 = t>>2 (0..63), granule g = t&3; 64B rows, swizzled
    const int row0 = t >> 2;
    const int g = t & 3;
    const uint32_t d0 = (uint32_t)row0 * 64 + (((uint32_t)g * 16) ^ (((uint32_t)row0 & 6) << 3));
    const uint32_t d1 = d0 + 4096;           // B rows 64..127
    const int gra = m0 + row0;
    const uint32_t szA = (gra < NN) ? 16u : 0u;
    const size_t aoff = (size_t)(gra < NN ? gra : NN - 1) * K + g * 8;
    const size_t boff0 = (size_t)(n0 + row0) * K + g * 8;
    const size_t boff1 = (size_t)(n0 + row0 + 64) * K + g * 8;

    // MMA fragment address constants
    const uint32_t fxor = ((uint32_t)(lane & 6)) << 3;
    const int ra = wr * 32 + (lane & 7) + ((lane >> 3) & 1) * 8;
    const uint32_t achk = ((uint32_t)(lane >> 4)) * 16;
    const int rb = wc * 32 + (lane & 7);
    const uint32_t bchk = ((uint32_t)((lane >> 3) & 1)) * 16;

#define FILL(ch, stg) do {                                                         \
    const unsigned short *ah_, *al_, *bh_, *bl_; int kb_;                          \
    if ((ch) < nc) { ah_ = a1h; al_ = a1l; bh_ = b1h; bl_ = b1l; kb_ = (ch) * 32; } \
    else           { ah_ = a2h; al_ = a2l; bh_ = b2h; bl_ = b2l; kb_ = ((ch) - nc) * 32; } \
    uint32_t s0_ = sb + (stg) * STAGE_B;                                           \
    CP16(s0_ + T_AH + d0, ah_ + aoff + kb_, szA);                                  \
    CP16(s0_ + T_AL + d0, al_ + aoff + kb_, szA);                                  \
    CP16(s0_ + T_BH + d0, bh_ + boff0 + kb_, 16u);                                 \
    CP16(s0_ + T_BH + d1, bh_ + boff1 + kb_, 16u);                                 \
    CP16(s0_ + T_BL + d0, bl_ + boff0 + kb_, 16u);                                 \
    CP16(s0_ + T_BL + d1, bl_ + boff1 + kb_, 16u);                                 \
    CP_COMMIT();                                                                   \
} while (0)

    FILL(0, 0);

    for (int ch = 0; ch < tot; ch++) {
        __syncthreads();
        if (ch + 1 < tot) { FILL(ch + 1, (ch + 1) & 1); CP_WAIT1(); }
        else              { CP_WAIT0(); }
        __syncthreads();

        const uint32_t s0 = sb + (ch & 1) * STAGE_B;
#pragma unroll
        for (int ks = 0; ks < 2; ks++) {
            uint32_t ahf[2][4], alf[2][4], bhf[4][2], blf[4][2];
#pragma unroll
            for (int mt = 0; mt < 2; mt++) {
                uint32_t base = s0 + (uint32_t)(ra + mt * 16) * 64;
                ldm4(ahf[mt], base + T_AH + (((uint32_t)(ks * 32) + achk) ^ fxor));
                ldm4(alf[mt], base + T_AL + (((uint32_t)(ks * 32) + achk) ^ fxor));
            }
#pragma unroll
            for (int nt = 0; nt < 4; nt++) {
                uint32_t base = s0 + (uint32_t)(rb + nt * 8) * 64;
                ldm2(bhf[nt], base + T_BH + (((uint32_t)(ks * 32) + bchk) ^ fxor));
                ldm2(blf[nt], base + T_BL + (((uint32_t)(ks * 32) + bchk) ^ fxor));
            }
#pragma unroll
            for (int mt = 0; mt < 2; mt++)
#pragma unroll
                for (int nt = 0; nt < 4; nt++) {
                    MMA_F16F32(acc[mt][nt], ahf[mt], bhf[nt]);
                    MMA_F16F32(acc[mt][nt], ahf[mt], blf[nt]);
                    MMA_F16F32(acc[mt][nt], alf[mt], bhf[nt]);
                }
        }
    }
#undef FILL

    // epilogue: bias; optional leaky; write hi/lo planes + f32 copy
#pragma unroll
    for (int mt = 0; mt < 2; mt++) {
        int r0 = m0 + wr * 32 + mt * 16 + (lane >> 2);
        int r1 = r0 + 8;
#pragma unroll
        for (int nt = 0; nt < 4; nt++) {
            int c0 = n0 + wc * 32 + nt * 8 + (lane & 3) * 2;
            float2 b2 = *(const float2*)(bias + c0);
            float v0 = acc[mt][nt][0] + b2.x;
            float v1 = acc[mt][nt][1] + b2.y;
            float v2 = acc[mt][nt][2] + b2.x;
            float v3 = acc[mt][nt][3] + b2.y;
            if (LEAKY) {
                v0 = v0 >= 0.f ? v0 : 0.01f * v0;
                v1 = v1 >= 0.f ? v1 : 0.01f * v1;
                v2 = v2 >= 0.f ? v2 : 0.01f * v2;
                v3 = v3 >= 0.f ? v3 : 0.01f * v3;
            }
            uint32_t hp, lp;
            if (r0 < NN) {
                size_t o = (size_t)r0 * DOUT + c0;
                split2(v0, v1, hp, lp);
                *(uint32_t*)(Oh + o) = hp;
                *(uint32_t*)(Ol + o) = lp;
                *(float2*)(Of + o) = make_float2(v0, v1);
            }
            if (r1 < NN) {
                size_t o = (size_t)r1 * DOUT + c0;
                split2(v2, v3, hp, lp);
                *(uint32_t*)(Oh + o) = hp;
                *(uint32_t*)(Ol + o) = lp;
                *(float2*)(Of + o) = make_float2(v2, v3);
            }
        }
    }
}

// ---------------- pool (binary-search bounds, f32 input) + head --------------
__global__ void k_pool(const float* __restrict__ H, const int* __restrict__ batch) {
    __shared__ int ss, ee;
    int gidx = blockIdx.x, f = threadIdx.x;
    if (f == 0) {
        int lo = 0, hi = NN;
        while (lo < hi) { int m = (lo + hi) >> 1; if (batch[m] < gidx) lo = m + 1; else hi = m; }
        ss = lo;
        hi = NN;
        while (lo < hi) { int m = (lo + hi) >> 1; if (batch[m] < gidx + 1) lo = m + 1; else hi = m; }
        ee = lo;
    }
    __syncthreads();
    int s = ss, e = ee;
    float sum = 0.f;
    for (int n = s; n < e; n++) sum += H[(size_t)n * 256 + f];
    int c = e - s; if (c < 1) c = 1;
    g_pool[gidx * 256 + f] = sum / (float)c;
}
__global__ void k_final(const float* __restrict__ Wlin, const float* __restrict__ blin,
                        float* __restrict__ out) {
    int idx = threadIdx.x;
    if (idx >= GG * 6) return;
    int g = idx / 6, o = idx % 6;
    float s = blin[o];
#pragma unroll 8
    for (int k = 0; k < 256; k++) s += g_pool[g * 256 + k] * Wlin[k * 6 + o];
    out[idx] = s;
}

// ---------------- launcher ----------------------------------------------------
extern "C" void kernel_launch(void* const* d_in, const int* in_sizes, int n_in,
                              void* d_out, int out_size) {
    const float* x     = (const float*)d_in[0];
    const int*   ei    = (const int*)d_in[1];
    const int*   batch = (const int*)d_in[2];
    WPtrs wp;
    const float* blp[6];
    for (int l = 0; l < 6; l++) {
        wp.w[2 * l]     = (const float*)d_in[3 + 3 * l];  // Wl
        blp[l]          = (const float*)d_in[4 + 3 * l];
        wp.w[2 * l + 1] = (const float*)d_in[5 + 3 * l];  // Wr
    }
    const float* Wlin = (const float*)d_in[21];
    const float* blin = (const float*)d_in[22];
    float* out = (float*)d_out;

    unsigned short *xh, *xl, *agh, *agl, *Ah, *Al, *Bh, *Bl, *wlh, *wll, *wrh, *wrl;
    float *f32;
    cudaGetSymbolAddress((void**)&xh, g_xh);   cudaGetSymbolAddress((void**)&xl, g_xl);
    cudaGetSymbolAddress((void**)&agh, g_agh); cudaGetSymbolAddress((void**)&agl, g_agl);
    cudaGetSymbolAddress((void**)&Ah, g_Ah);   cudaGetSymbolAddress((void**)&Al, g_Al);
    cudaGetSymbolAddress((void**)&Bh, g_Bh);   cudaGetSymbolAddress((void**)&Bl, g_Bl);
    cudaGetSymbolAddress((void**)&wlh, g_wlh); cudaGetSymbolAddress((void**)&wll, g_wll);
    cudaGetSymbolAddress((void**)&wrh, g_wrh); cudaGetSymbolAddress((void**)&wrl, g_wrl);
    cudaGetSymbolAddress((void**)&f32, g_f32);

    cudaFuncSetAttribute(k_gemm_tc<true>,  cudaFuncAttributeMaxDynamicSharedMemorySize, SMEM_BYTES);
    cudaFuncSetAttribute(k_gemm_tc<false>, cudaFuncAttributeMaxDynamicSharedMemorySize, SMEM_BYTES);

    const int din[6]  = {128, 256, 256, 512, 512, 256};
    const int dout[6] = {256, 256, 512, 512, 256, 256};
    const int woff[6] = {0, 32768, 98304, 229376, 491520, 622592};

    // setup
    k_cvtall<<<dim3(1250, 13), 256>>>(x, wp);
    k_count<<<(EE + 255) / 256, 256>>>(ei);
    k_scan<<<1, 1024>>>();
    k_fillcsr<<<(EE + 255) / 256, 256>>>(ei);

    const unsigned short* inh = xh; const unsigned short* inl = xl;
    const float* inf = x;  // layer 0 aggregates the raw f32 input
    for (int l = 0; l < 6; l++) {
        unsigned short* oh = (l & 1) ? Bh : Ah;
        unsigned short* ol = (l & 1) ? Bl : Al;
        dim3 agrid((NN + 7) / 8, din[l] >> 7);
        k_agg<<<agrid, 256>>>(inf, agh, agl, din[l]);
        dim3 grid(dout[l] / 128, (NN + 63) / 64);
        if (l < 5)
            k_gemm_tc<true><<<grid, 256, SMEM_BYTES>>>(
                agh, agl, inh, inl,
                wlh + woff[l], wll + woff[l], wrh + woff[l], wrl + woff[l],
                blp[l], oh, ol, f32, din[l], dout[l]);
        else
            k_gemm_tc<false><<<grid, 256, SMEM_BYTES>>>(
                agh, agl, inh, inl,
                wlh + woff[l], wll + woff[l], wrh + woff[l], wrl + woff[l],
                blp[l], oh, ol, f32, din[l], dout[l]);
        inh = oh; inl = ol; inf = f32;
    }
    k_pool<<<GG, 256>>>(f32, batch);
    k_final<<<1, 384>>>(Wlin, blin, out);
}